// round 16
// baseline (speedup 1.0000x reference)
#include <cuda_runtime.h>
#include <cstdint>

#define KROWS 8192
#define DDIM  256
#define CAP   256
#define NSEL  30
#define NLAB  64
#define NBLK  1024          // 8-row work blocks
#define MEGA_GRID 888       // persistent CTAs (work-stealing absorbs residency)
// pass iff bits >= 2^32 - 2^26  (p = 1/64)
#define THRESH 0xFC000000u

// ---------------- scratch (static device globals; no allocation) ----------------
__device__ __align__(16) float         d_fnorm[KROWS * DDIM];
__device__ __align__(16) unsigned char d_lab8[KROWS];
__device__ int   d_counts[NLAB];
__device__ int   d_offsets[NLAB];
__device__ int   d_grows[KROWS];
__device__ float d_num[KROWS];
__device__ float d_negsum[KROWS];
__device__ float d_partial[32];
__device__ int   d_work;            // persistent-kernel block counter

// ---------------- threefry2x32-20, key = (0, 42), partitionable out0^out1 ----------------
// Dual-stream (sweep) and single-stream (survivor recompute) variants; pure SHF rotations.
__device__ __forceinline__ void threefry_xor2(uint32_t ia, uint32_t ib,
                                              uint32_t& oa, uint32_t& ob) {
    const uint32_t ks1 = 42u, ks2 = 0x1BD11BF0u;   // 0 ^ 42 ^ 0x1BD11BDA
    uint32_t a0 = 0u, a1 = ia + ks1;
    uint32_t b0 = 0u, b1 = ib + ks1;
#define R2(r) { a0 += a1; a1 = __funnelshift_l(a1, a1, (r)) ^ a0; \
                b0 += b1; b1 = __funnelshift_l(b1, b1, (r)) ^ b0; }
    R2(13) R2(15) R2(26) R2(6)
    a0 += ks1; a1 += ks2 + 1u;  b0 += ks1; b1 += ks2 + 1u;
    R2(17) R2(29) R2(16) R2(24)
    a0 += ks2; a1 += 2u;        b0 += ks2; b1 += 2u;
    R2(13) R2(15) R2(26) R2(6)
    a1 += ks1 + 3u;             b1 += ks1 + 3u;          // x0 += ks0(=0)
    R2(17) R2(29) R2(16) R2(24)
    a0 += ks1; a1 += ks2 + 4u;  b0 += ks1; b1 += ks2 + 4u;
    R2(13) R2(15) R2(26) R2(6)
    a0 += ks2; a1 += 5u;        b0 += ks2; b1 += 5u;
#undef R2
    oa = a0 ^ a1;
    ob = b0 ^ b1;
}

__device__ __forceinline__ uint32_t threefry_xor1(uint32_t i1) {
    const uint32_t ks1 = 42u, ks2 = 0x1BD11BF0u;
    uint32_t x0 = 0u, x1 = i1 + ks1;
#define R1(r) { x0 += x1; x1 = __funnelshift_l(x1, x1, (r)) ^ x0; }
    R1(13) R1(15) R1(26) R1(6)
    x0 += ks1; x1 += ks2 + 1u;
    R1(17) R1(29) R1(16) R1(24)
    x0 += ks2; x1 += 2u;
    R1(13) R1(15) R1(26) R1(6)
    x1 += ks1 + 3u;
    R1(17) R1(29) R1(16) R1(24)
    x0 += ks1; x1 += ks2 + 4u;
    R1(13) R1(15) R1(26) R1(6)
    x0 += ks2; x1 += 5u;
#undef R1
    return x0 ^ x1;
}

// ---------------- setup A: dtype detect + labels + histogram (1 CTA) ----------------
__global__ void k_setupA(const int* __restrict__ raw) {
    __shared__ int s_is64;
    __shared__ int s_cnt[NLAB];
    int t = threadIdx.x;                      // 1024 threads
    if (t == 0) {
        // int64 LE labels in [0,64): every high word is 0; for int32 labels the
        // odd words are labels (all-zero prob (1/64)^31 ~ 0). Reads only the
        // first 8192 int32 words (safe for both layouts).
        int odd = 0;
        for (int p = 0; p < 32; p++) odd |= raw[2 * p + 1];
        s_is64 = (odd == 0);
        d_work = 0;                           // reset persistent counter every launch
    }
    if (t < NLAB) s_cnt[t] = 0;
    if (t < 32) d_partial[t] = 0.f;
    __syncthreads();
    int is64 = s_is64;
    for (int i = t; i < KROWS; i += 1024) {
        int l = (is64 ? raw[2 * i] : raw[i]) & (NLAB - 1);
        d_lab8[i] = (unsigned char)l;
        atomicAdd(&s_cnt[l], 1);
    }
    __syncthreads();
    if (t < NLAB) d_counts[t] = s_cnt[t];
}

// ---------------- setup B: per-label group fill (64 CTAs, 256 thr) ----------------
// Deterministic: thread t covers rows [32t, 32t+32); ascending order preserved.
__global__ void k_setupB() {
    __shared__ int s_pre[256];
    __shared__ int s_base;
    int lbl = blockIdx.x;
    int t = threadIdx.x;
    if (t == 0) {
        int a = 0;
        for (int i = 0; i < lbl; i++) a += d_counts[i];
        s_base = a;
        d_offsets[lbl] = a;
    }
    unsigned mbits = 0;
    int start = t * 32;
#pragma unroll 8
    for (int i = 0; i < 32; i++)
        if ((int)d_lab8[start + i] == lbl) mbits |= 1u << i;
    int my = __popc(mbits);
    // exclusive prefix scan over 256 threads (warp shuffle + smem)
    int lane = t & 31, w = t >> 5;
    int x = my;
#pragma unroll
    for (int o = 1; o < 32; o <<= 1) {
        int y = __shfl_up_sync(0xffffffffu, x, o);
        if (lane >= o) x += y;
    }
    if (lane == 31) s_pre[w] = x;
    __syncthreads();
    if (t == 0) {
        int a = 0;
        for (int i = 0; i < 8; i++) { int c = s_pre[i]; s_pre[i] = a; a += c; }
    }
    __syncthreads();
    int pos = s_base + s_pre[w] + (x - my);   // exclusive prefix for this thread
    while (mbits) {
        int i = __ffs(mbits) - 1;
        mbits &= mbits - 1;
        d_grows[pos++] = start + i;
    }
}

// ---------------- L2 normalize (warp per row, float4) ----------------
__global__ void k_norm(const float* __restrict__ x) {
    int w = (blockIdx.x * blockDim.x + threadIdx.x) >> 5;
    int lane = threadIdx.x & 31;
    if (w >= KROWS) return;
    const float4* x4 = (const float4*)(x) + w * 64;
    float4* o4 = (float4*)(d_fnorm) + w * 64;
    float4 a = x4[lane], b = x4[lane + 32];
    float ss = a.x * a.x + a.y * a.y + a.z * a.z + a.w * a.w
             + b.x * b.x + b.y * b.y + b.z * b.z + b.w * b.w;
#pragma unroll
    for (int o = 16; o; o >>= 1) ss += __shfl_xor_sync(0xffffffffu, ss, o);
    float sc = 1.0f / fmaxf(sqrtf(ss), 1e-12f);
    a.x *= sc; a.y *= sc; a.z *= sc; a.w *= sc;
    b.x *= sc; b.y *= sc; b.z *= sc; b.w *= sc;
    o4[lane] = a; o4[lane + 32] = b;
}

__device__ __forceinline__ float dot8(float4 a0, float4 a1, float4 b0, float4 b1) {
    return a0.x * b0.x + a0.y * b0.y + a0.z * b0.z + a0.w * b0.w
         + a1.x * b1.x + a1.y * b1.y + a1.z * b1.z + a1.w * b1.w;
}

// ---------------- mega (persistent): dynamic 8-row blocks; per row:
// ballot threefry sweep + survivor recompute + top-30 negatives + top-6 positives ----
__global__ __launch_bounds__(256, 5) void k_mega() {
    __shared__ unsigned char slab[KROWS];     // labels (loaded once per CTA)
    __shared__ unsigned s_bal[8][256];        // per-iteration pass ballots
    __shared__ unsigned s_dense[8][CAP];      // dense label-filtered survivor keys
    __shared__ int s_blk;
    int tid  = threadIdx.x;
    int wl   = tid >> 5;
    int lane = tid & 31;

    for (int i = tid; i < KROWS; i += 256) slab[i] = d_lab8[i];
    __syncthreads();

    while (true) {
        if (tid == 0) s_blk = atomicAdd(&d_work, 1);
        __syncthreads();
        int blk = s_blk;
        if (blk >= NBLK) break;

        int row = blk * 8 + wl;
        unsigned char lr = slab[row];
        unsigned base = (unsigned)row * 8192u + (unsigned)lane;
        unsigned* bal = s_bal[wl];
        unsigned* dn  = s_dense[wl];

        // ---- phase 1 sweep: dual-stream threefry; record pass ballots only.
        // word w covers cols [32w, 32w+32); bit b of bal[w] => col 32w+b passed.
#pragma unroll 2
        for (int k = 0; k < 128; k++) {
            uint32_t bA, bB;
            threefry_xor2(base + 32u * (unsigned)k,
                          base + 32u * (unsigned)(k + 128), bA, bB);
            unsigned mA = __ballot_sync(0xffffffffu, bA >= THRESH);
            unsigned mB = __ballot_sync(0xffffffffu, bB >= THRESH);
            bal[k]       = mA;     // same value from all lanes; write collapses
            bal[k + 128] = mB;
        }
        __syncwarp();

        // ---- survivor extraction: lane owns words {lane, lane+32, ...} ----
        // pass 1: count label-filtered keeps
        int keep = 0;
#pragma unroll
        for (int wi = 0; wi < 8; wi++) {
            unsigned m = bal[wi * 32 + lane];
            unsigned cbase = 32u * (wi * 32 + lane);
            while (m) {
                int b = __ffs(m) - 1; m &= m - 1;
                if (slab[cbase + b] != lr) keep++;
            }
        }
        // exclusive warp scan for dense positions
        int x = keep;
#pragma unroll
        for (int o = 1; o < 32; o <<= 1) {
            int y = __shfl_up_sync(0xffffffffu, x, o);
            if (lane >= o) x += y;
        }
        int pos = x - keep;
        int n = min(__shfl_sync(0xffffffffu, x, 31), CAP);
        // pass 2: recompute hash for keepers, emit keys (order irrelevant)
#pragma unroll
        for (int wi = 0; wi < 8; wi++) {
            unsigned m = bal[wi * 32 + lane];
            unsigned cbase = 32u * (wi * 32 + lane);
            while (m) {
                int b = __ffs(m) - 1; m &= m - 1;
                unsigned col = cbase + b;
                if (slab[col] != lr) {
                    uint32_t bits = threefry_xor1((unsigned)row * 8192u + col);
                    if (pos < CAP)
                        dn[pos] = (((bits - THRESH) << 4) & 0xFFFFE000u) | (8191u - col);
                    pos++;
                }
            }
        }
        __syncwarp();

        // ---- phase 2a: exact top-30 selection (no gmem); keys -> dn[0..29] ----
        {
            unsigned e[CAP / 32];
#pragma unroll
            for (int k = 0; k < CAP / 32; k++) {
                int idx = lane + 32 * k;
                e[k] = (idx < n) ? dn[idx] : 0u;
            }
#pragma unroll
            for (int s = 0; s < NSEL; s++) {
                unsigned lm = 0u; int lk = -1;
#pragma unroll
                for (int k = 0; k < CAP / 32; k++)
                    if (e[k] > lm) { lm = e[k]; lk = k; }
                unsigned wm = lm;
#pragma unroll
                for (int o = 16; o; o >>= 1)
                    wm = max(wm, __shfl_xor_sync(0xffffffffu, wm, o));
                if (lk >= 0 && lm == wm) e[lk] = 0u;  // unique keys: one lane clears
                if (lane == 0) dn[s] = wm;            // 0 if < s survivors (never in practice)
            }
        }
        __syncwarp();

        // ---- phase 2b: gather dots for the 30 keys, 3-way ILP batches ----
        {
            const float4* f4 = (const float4*)(d_fnorm) + row * 64;
            float4 a0 = f4[lane], a1 = f4[lane + 32];
            float acc = 0.f;
#pragma unroll
            for (int s = 0; s < NSEL; s += 3) {
                unsigned k0 = dn[s], k1 = dn[s + 1], k2 = dn[s + 2];
                const float4* c0 = (const float4*)(d_fnorm) + (8191 - (int)(k0 & 0x1FFFu)) * 64;
                const float4* c1 = (const float4*)(d_fnorm) + (8191 - (int)(k1 & 0x1FFFu)) * 64;
                const float4* c2 = (const float4*)(d_fnorm) + (8191 - (int)(k2 & 0x1FFFu)) * 64;
                float4 x0 = __ldg(c0 + lane), y0 = __ldg(c0 + lane + 32);
                float4 x1 = __ldg(c1 + lane), y1 = __ldg(c1 + lane + 32);
                float4 x2 = __ldg(c2 + lane), y2 = __ldg(c2 + lane + 32);
                float p0 = dot8(a0, a1, x0, y0);
                float p1 = dot8(a0, a1, x1, y1);
                float p2 = dot8(a0, a1, x2, y2);
#pragma unroll
                for (int o = 16; o; o >>= 1) {       // three interleaved shfl chains
                    p0 += __shfl_xor_sync(0xffffffffu, p0, o);
                    p1 += __shfl_xor_sync(0xffffffffu, p1, o);
                    p2 += __shfl_xor_sync(0xffffffffu, p2, o);
                }
                if (k0) acc += __expf(10.f * p0 - 10.f);  // exp(sim/T - max); shift cancels
                if (k1) acc += __expf(10.f * p1 - 10.f);
                if (k2) acc += __expf(10.f * p2 - 10.f);
            }
            if (lane == 0) d_negsum[row] = acc;
        }

        // ---- phase 3: top-6 same-label sims for anchor d_grows[row], 3-way ILP ----
        {
            int anchor = d_grows[row];
            int lbl  = (int)slab[anchor];
            int off  = d_offsets[lbl];
            int gcnt = d_counts[lbl];

            const float4* g4 = (const float4*)(d_fnorm) + anchor * 64;
            float4 a0 = g4[lane], a1 = g4[lane + 32];

            float v[6];
#pragma unroll
            for (int k = 0; k < 6; k++) v[k] = -3.0e38f;

#define INS(P) { float a_ = (P); \
    _Pragma("unroll") for (int q_ = 0; q_ < 6; q_++) { \
        float hi_ = fmaxf(v[q_], a_); float lo_ = fminf(v[q_], a_); \
        v[q_] = hi_; a_ = lo_; } }

            for (int j0 = 0; j0 < gcnt; j0 += 3) {
                int c0 = d_grows[off + j0];
                int c1 = (j0 + 1 < gcnt) ? d_grows[off + j0 + 1] : anchor;
                int c2 = (j0 + 2 < gcnt) ? d_grows[off + j0 + 2] : anchor;
                const float4* q0 = (const float4*)(d_fnorm) + c0 * 64;
                const float4* q1 = (const float4*)(d_fnorm) + c1 * 64;
                const float4* q2 = (const float4*)(d_fnorm) + c2 * 64;
                float4 x0 = __ldg(q0 + lane), y0 = __ldg(q0 + lane + 32);
                float4 x1 = __ldg(q1 + lane), y1 = __ldg(q1 + lane + 32);
                float4 x2 = __ldg(q2 + lane), y2 = __ldg(q2 + lane + 32);
                float p0 = dot8(a0, a1, x0, y0);
                float p1 = dot8(a0, a1, x1, y1);
                float p2 = dot8(a0, a1, x2, y2);
#pragma unroll
                for (int o = 16; o; o >>= 1) {
                    p0 += __shfl_xor_sync(0xffffffffu, p0, o);
                    p1 += __shfl_xor_sync(0xffffffffu, p1, o);
                    p2 += __shfl_xor_sync(0xffffffffu, p2, o);
                }
                if (c0 != anchor && p0 > v[5]) INS(p0);
                if (c1 != anchor && p1 > v[5]) INS(p1);
                if (c2 != anchor && p2 > v[5]) INS(p2);
            }
#undef INS

            int m = min(gcnt - 1, 6);
            float num = 0.f;
#pragma unroll
            for (int k = 0; k < 6; k++)
                if (k < m) num += __expf(10.f * v[k] - 10.f);
            if (lane == 0) d_num[anchor] = num;
        }

        __syncthreads();   // protect s_blk / s_bal before next block iteration
    }
}

// ---------------- two-stage deterministic reduction ----------------
__global__ void k_red1() {
    __shared__ float sm[256];
    int i = blockIdx.x * 256 + threadIdx.x;   // 32 CTAs x 256 = 8192
    float num = d_num[i];
    float den = num + d_negsum[i];
    float r = fmaxf(num / den, 1e-8f);
    sm[threadIdx.x] = -__logf(r);
    __syncthreads();
    for (int s = 128; s; s >>= 1) {
        if (threadIdx.x < s) sm[threadIdx.x] += sm[threadIdx.x + s];
        __syncthreads();
    }
    if (threadIdx.x == 0) d_partial[blockIdx.x] = sm[0];
}

__global__ void k_red2(float* __restrict__ out) {
    int lane = threadIdx.x;
    float a = d_partial[lane];                // 32 values
#pragma unroll
    for (int o = 16; o; o >>= 1) a += __shfl_xor_sync(0xffffffffu, a, o);
    if (lane == 0) out[0] = a * (1.0f / 8192.0f);
}

// ---------------- launch ----------------
extern "C" void kernel_launch(void* const* d_in, const int* in_sizes, int n_in,
                              void* d_out, int out_size) {
    const float* features = (const float*)d_in[0];
    const int*   labraw   = (const int*)d_in[1];
    float* out = (float*)d_out;

    k_setupA<<<1, 1024>>>(labraw);      // 1
    k_norm  <<<1024, 256>>>(features);  // 2
    k_setupB<<<64, 256>>>();            // 3
    k_mega  <<<MEGA_GRID, 256>>>();     // 4  (ncu profiles launch #4)
    k_red1  <<<32, 256>>>();            // 5
    k_red2  <<<1, 32>>>(out);           // 6
}

// round 17
// speedup vs baseline: 1.0527x; 1.0527x over previous
#include <cuda_runtime.h>
#include <cstdint>

#define KROWS 8192
#define DDIM  256
#define CAP   192           // dense survivor cap (row mean ~126, max ~173)
#define NSEL  30
#define NLAB  64
#define NBLK  1024          // 8-row work blocks
#define MEGA_GRID 888       // persistent CTAs (work-stealing absorbs residency)
#define LCAP  20            // per-lane candidate cap (Poisson mean 4)
#define LSTR  21            // lane buffer stride (odd => conflict-free)
// pass iff bits >= 2^32 - 2^26  (p = 1/64)
#define THRESH 0xFC000000u

// ---------------- scratch (static device globals; no allocation) ----------------
__device__ __align__(16) float         d_fnorm[KROWS * DDIM];
__device__ __align__(16) unsigned char d_lab8[KROWS];
__device__ int   d_counts[NLAB];
__device__ int   d_offsets[NLAB];
__device__ int   d_grows[KROWS];
__device__ float d_num[KROWS];
__device__ float d_negsum[KROWS];
__device__ float d_partial[32];
__device__ int   d_work;            // persistent-kernel block counter

// ---------------- threefry2x32-20, key = (0, 42), partitionable out0^out1 ----------------
// Two independent cipher streams per thread, pure funnel-shift rotations (proven best).
__device__ __forceinline__ void threefry_xor2(uint32_t ia, uint32_t ib,
                                              uint32_t& oa, uint32_t& ob) {
    const uint32_t ks1 = 42u, ks2 = 0x1BD11BF0u;   // 0 ^ 42 ^ 0x1BD11BDA
    uint32_t a0 = 0u, a1 = ia + ks1;
    uint32_t b0 = 0u, b1 = ib + ks1;
#define R2(r) { a0 += a1; a1 = __funnelshift_l(a1, a1, (r)) ^ a0; \
                b0 += b1; b1 = __funnelshift_l(b1, b1, (r)) ^ b0; }
    R2(13) R2(15) R2(26) R2(6)
    a0 += ks1; a1 += ks2 + 1u;  b0 += ks1; b1 += ks2 + 1u;
    R2(17) R2(29) R2(16) R2(24)
    a0 += ks2; a1 += 2u;        b0 += ks2; b1 += 2u;
    R2(13) R2(15) R2(26) R2(6)
    a1 += ks1 + 3u;             b1 += ks1 + 3u;          // x0 += ks0(=0)
    R2(17) R2(29) R2(16) R2(24)
    a0 += ks1; a1 += ks2 + 4u;  b0 += ks1; b1 += ks2 + 4u;
    R2(13) R2(15) R2(26) R2(6)
    a0 += ks2; a1 += 5u;        b0 += ks2; b1 += 5u;
#undef R2
    oa = a0 ^ a1;
    ob = b0 ^ b1;
}

// ---------------- setup A: dtype detect + labels + histogram (1 CTA) ----------------
__global__ void k_setupA(const int* __restrict__ raw) {
    __shared__ int s_is64;
    __shared__ int s_cnt[NLAB];
    int t = threadIdx.x;                      // 1024 threads
    if (t == 0) {
        // int64 LE labels in [0,64): every high word is 0; for int32 labels the
        // odd words are labels (all-zero prob (1/64)^31 ~ 0). Reads only the
        // first 8192 int32 words (safe for both layouts).
        int odd = 0;
        for (int p = 0; p < 32; p++) odd |= raw[2 * p + 1];
        s_is64 = (odd == 0);
        d_work = 0;                           // reset persistent counter every launch
    }
    if (t < NLAB) s_cnt[t] = 0;
    if (t < 32) d_partial[t] = 0.f;
    __syncthreads();
    int is64 = s_is64;
    for (int i = t; i < KROWS; i += 1024) {
        int l = (is64 ? raw[2 * i] : raw[i]) & (NLAB - 1);
        d_lab8[i] = (unsigned char)l;
        atomicAdd(&s_cnt[l], 1);
    }
    __syncthreads();
    if (t < NLAB) d_counts[t] = s_cnt[t];
}

// ---------------- setup B: per-label group fill (64 CTAs, 256 thr) ----------------
// Deterministic: thread t covers rows [32t, 32t+32); ascending order preserved.
__global__ void k_setupB() {
    __shared__ int s_pre[256];
    __shared__ int s_base;
    int lbl = blockIdx.x;
    int t = threadIdx.x;
    if (t == 0) {
        int a = 0;
        for (int i = 0; i < lbl; i++) a += d_counts[i];
        s_base = a;
        d_offsets[lbl] = a;
    }
    unsigned mbits = 0;
    int start = t * 32;
#pragma unroll 8
    for (int i = 0; i < 32; i++)
        if ((int)d_lab8[start + i] == lbl) mbits |= 1u << i;
    int my = __popc(mbits);
    // exclusive prefix scan over 256 threads (warp shuffle + smem)
    int lane = t & 31, w = t >> 5;
    int x = my;
#pragma unroll
    for (int o = 1; o < 32; o <<= 1) {
        int y = __shfl_up_sync(0xffffffffu, x, o);
        if (lane >= o) x += y;
    }
    if (lane == 31) s_pre[w] = x;
    __syncthreads();
    if (t == 0) {
        int a = 0;
        for (int i = 0; i < 8; i++) { int c = s_pre[i]; s_pre[i] = a; a += c; }
    }
    __syncthreads();
    int pos = s_base + s_pre[w] + (x - my);   // exclusive prefix for this thread
    while (mbits) {
        int i = __ffs(mbits) - 1;
        mbits &= mbits - 1;
        d_grows[pos++] = start + i;
    }
}

// ---------------- L2 normalize (warp per row, float4) ----------------
__global__ void k_norm(const float* __restrict__ x) {
    int w = (blockIdx.x * blockDim.x + threadIdx.x) >> 5;
    int lane = threadIdx.x & 31;
    if (w >= KROWS) return;
    const float4* x4 = (const float4*)(x) + w * 64;
    float4* o4 = (float4*)(d_fnorm) + w * 64;
    float4 a = x4[lane], b = x4[lane + 32];
    float ss = a.x * a.x + a.y * a.y + a.z * a.z + a.w * a.w
             + b.x * b.x + b.y * b.y + b.z * b.z + b.w * b.w;
#pragma unroll
    for (int o = 16; o; o >>= 1) ss += __shfl_xor_sync(0xffffffffu, ss, o);
    float sc = 1.0f / fmaxf(sqrtf(ss), 1e-12f);
    a.x *= sc; a.y *= sc; a.z *= sc; a.w *= sc;
    b.x *= sc; b.y *= sc; b.z *= sc; b.w *= sc;
    o4[lane] = a; o4[lane + 32] = b;
}

__device__ __forceinline__ float dot8(float4 a0, float4 a1, float4 b0, float4 b1) {
    return a0.x * b0.x + a0.y * b0.y + a0.z * b0.z + a0.w * b0.w
         + a1.x * b1.x + a1.y * b1.y + a1.z * b1.z + a1.w * b1.w;
}

// ---------------- mega (persistent): dynamic 8-row blocks; per row:
// threefry sweep (lane-local candidates, labels deferred) + top-30 negatives
// + top-6 positives ----------------
__global__ __launch_bounds__(256, 5) void k_mega() {
    __shared__ unsigned char slab[KROWS];       // labels (loaded once)
    __shared__ unsigned s_lane[8][32 * LSTR];   // per-lane candidate buffers
    __shared__ unsigned s_dense[8][CAP];        // dense label-filtered keys
    __shared__ int s_blk;
    int tid  = threadIdx.x;
    int wl   = tid >> 5;
    int lane = tid & 31;

    for (int i = tid; i < KROWS; i += 256) slab[i] = d_lab8[i];
    __syncthreads();

    while (true) {
        if (tid == 0) s_blk = atomicAdd(&d_work, 1);
        __syncthreads();
        int blk = s_blk;
        if (blk >= NBLK) break;

        int row = blk * 8 + wl;
        unsigned char lr = slab[row];
        unsigned base = (unsigned)row * 8192u + (unsigned)lane;
        unsigned* sl = &s_lane[wl][lane * LSTR];
        unsigned* dn = s_dense[wl];
        int c = 0;

        // ---- phase 1: dual-stream threefry + threshold; lane-local append.
        // key = ((bits-THRESH)<<4 & 0xFFFFE000) | (8191-col)  [identical to
        // ((bits>>9)-0x7E0000)<<13 | (8191-col)]. Labels filtered later.
#pragma unroll 2
        for (int k = 0; k < 128; k++) {
            uint32_t bA, bB;
            threefry_xor2(base + 32u * (unsigned)k,
                          base + 32u * (unsigned)(k + 128), bA, bB);
            unsigned cA = 8191u - 32u * (unsigned)k - (unsigned)lane;
            if (bA >= THRESH) {
                if (c < LCAP) sl[c] = (((bA - THRESH) << 4) & 0xFFFFE000u) | cA;
                c++;
            }
            if (bB >= THRESH) {
                if (c < LCAP) sl[c] = (((bB - THRESH) << 4) & 0xFFFFE000u) | (cA - 4096u);
                c++;
            }
        }
        c = min(c, LCAP);
        __syncwarp();

        // ---- compaction: label-filter in place, warp scan, write dense ----
        int n;
        {
            int keep = 0;
            for (int i = 0; i < c; i++) {
                unsigned key = sl[i];
                unsigned col = 8191u - (key & 0x1FFFu);
                if (slab[col] != lr) sl[keep++] = key;
            }
            int x = keep;
#pragma unroll
            for (int o = 1; o < 32; o <<= 1) {
                int y = __shfl_up_sync(0xffffffffu, x, o);
                if (lane >= o) x += y;
            }
            int pref = x - keep;
            for (int i = 0; i < keep; i++) {
                int p = pref + i;
                if (p < CAP) dn[p] = sl[i];
            }
            n = min(__shfl_sync(0xffffffffu, x, 31), CAP);
        }
        __syncwarp();

        // ---- phase 2a: exact top-30 selection (no gmem); keys -> dn[0..29] ----
        {
            unsigned e[CAP / 32];
#pragma unroll
            for (int k = 0; k < CAP / 32; k++) {
                int idx = lane + 32 * k;
                e[k] = (idx < n) ? dn[idx] : 0u;
            }
#pragma unroll
            for (int s = 0; s < NSEL; s++) {
                unsigned lm = 0u; int lk = -1;
#pragma unroll
                for (int k = 0; k < CAP / 32; k++)
                    if (e[k] > lm) { lm = e[k]; lk = k; }
                unsigned wm = lm;
#pragma unroll
                for (int o = 16; o; o >>= 1)
                    wm = max(wm, __shfl_xor_sync(0xffffffffu, wm, o));
                if (lk >= 0 && lm == wm) e[lk] = 0u;  // unique keys: one lane clears
                if (lane == 0) dn[s] = wm;            // 0 if < s survivors (never in practice)
            }
        }
        __syncwarp();

        // ---- phase 2b: gather dots for the 30 keys, 3-way ILP batches ----
        {
            const float4* f4 = (const float4*)(d_fnorm) + row * 64;
            float4 a0 = f4[lane], a1 = f4[lane + 32];
            float acc = 0.f;
#pragma unroll
            for (int s = 0; s < NSEL; s += 3) {
                unsigned k0 = dn[s], k1 = dn[s + 1], k2 = dn[s + 2];
                const float4* c0 = (const float4*)(d_fnorm) + (8191 - (int)(k0 & 0x1FFFu)) * 64;
                const float4* c1 = (const float4*)(d_fnorm) + (8191 - (int)(k1 & 0x1FFFu)) * 64;
                const float4* c2 = (const float4*)(d_fnorm) + (8191 - (int)(k2 & 0x1FFFu)) * 64;
                float4 x0 = __ldg(c0 + lane), y0 = __ldg(c0 + lane + 32);
                float4 x1 = __ldg(c1 + lane), y1 = __ldg(c1 + lane + 32);
                float4 x2 = __ldg(c2 + lane), y2 = __ldg(c2 + lane + 32);
                float p0 = dot8(a0, a1, x0, y0);
                float p1 = dot8(a0, a1, x1, y1);
                float p2 = dot8(a0, a1, x2, y2);
#pragma unroll
                for (int o = 16; o; o >>= 1) {       // three interleaved shfl chains
                    p0 += __shfl_xor_sync(0xffffffffu, p0, o);
                    p1 += __shfl_xor_sync(0xffffffffu, p1, o);
                    p2 += __shfl_xor_sync(0xffffffffu, p2, o);
                }
                if (k0) acc += __expf(10.f * p0 - 10.f);  // exp(sim/T - max); shift cancels
                if (k1) acc += __expf(10.f * p1 - 10.f);
                if (k2) acc += __expf(10.f * p2 - 10.f);
            }
            if (lane == 0) d_negsum[row] = acc;
        }

        // ---- phase 3: top-6 same-label sims for anchor d_grows[row], 3-way ILP ----
        {
            int anchor = d_grows[row];
            int lbl  = (int)slab[anchor];
            int off  = d_offsets[lbl];
            int gcnt = d_counts[lbl];

            const float4* g4 = (const float4*)(d_fnorm) + anchor * 64;
            float4 a0 = g4[lane], a1 = g4[lane + 32];

            float v[6];
#pragma unroll
            for (int k = 0; k < 6; k++) v[k] = -3.0e38f;

#define INS(P) { float a_ = (P); \
    _Pragma("unroll") for (int q_ = 0; q_ < 6; q_++) { \
        float hi_ = fmaxf(v[q_], a_); float lo_ = fminf(v[q_], a_); \
        v[q_] = hi_; a_ = lo_; } }

            for (int j0 = 0; j0 < gcnt; j0 += 3) {
                int c0 = d_grows[off + j0];
                int c1 = (j0 + 1 < gcnt) ? d_grows[off + j0 + 1] : anchor;
                int c2 = (j0 + 2 < gcnt) ? d_grows[off + j0 + 2] : anchor;
                const float4* q0 = (const float4*)(d_fnorm) + c0 * 64;
                const float4* q1 = (const float4*)(d_fnorm) + c1 * 64;
                const float4* q2 = (const float4*)(d_fnorm) + c2 * 64;
                float4 x0 = __ldg(q0 + lane), y0 = __ldg(q0 + lane + 32);
                float4 x1 = __ldg(q1 + lane), y1 = __ldg(q1 + lane + 32);
                float4 x2 = __ldg(q2 + lane), y2 = __ldg(q2 + lane + 32);
                float p0 = dot8(a0, a1, x0, y0);
                float p1 = dot8(a0, a1, x1, y1);
                float p2 = dot8(a0, a1, x2, y2);
#pragma unroll
                for (int o = 16; o; o >>= 1) {
                    p0 += __shfl_xor_sync(0xffffffffu, p0, o);
                    p1 += __shfl_xor_sync(0xffffffffu, p1, o);
                    p2 += __shfl_xor_sync(0xffffffffu, p2, o);
                }
                if (c0 != anchor && p0 > v[5]) INS(p0);
                if (c1 != anchor && p1 > v[5]) INS(p1);
                if (c2 != anchor && p2 > v[5]) INS(p2);
            }
#undef INS

            int m = min(gcnt - 1, 6);
            float num = 0.f;
#pragma unroll
            for (int k = 0; k < 6; k++)
                if (k < m) num += __expf(10.f * v[k] - 10.f);
            if (lane == 0) d_num[anchor] = num;
        }

        __syncthreads();   // protect s_blk before next block iteration
    }
}

// ---------------- two-stage deterministic reduction ----------------
__global__ void k_red1() {
    __shared__ float sm[256];
    int i = blockIdx.x * 256 + threadIdx.x;   // 32 CTAs x 256 = 8192
    float num = d_num[i];
    float den = num + d_negsum[i];
    float r = fmaxf(num / den, 1e-8f);
    sm[threadIdx.x] = -__logf(r);
    __syncthreads();
    for (int s = 128; s; s >>= 1) {
        if (threadIdx.x < s) sm[threadIdx.x] += sm[threadIdx.x + s];
        __syncthreads();
    }
    if (threadIdx.x == 0) d_partial[blockIdx.x] = sm[0];
}

__global__ void k_red2(float* __restrict__ out) {
    int lane = threadIdx.x;
    float a = d_partial[lane];                // 32 values
#pragma unroll
    for (int o = 16; o; o >>= 1) a += __shfl_xor_sync(0xffffffffu, a, o);
    if (lane == 0) out[0] = a * (1.0f / 8192.0f);
}

// ---------------- launch ----------------
extern "C" void kernel_launch(void* const* d_in, const int* in_sizes, int n_in,
                              void* d_out, int out_size) {
    const float* features = (const float*)d_in[0];
    const int*   labraw   = (const int*)d_in[1];
    float* out = (float*)d_out;

    k_setupA<<<1, 1024>>>(labraw);      // 1
    k_norm  <<<1024, 256>>>(features);  // 2
    k_setupB<<<64, 256>>>();            // 3
    k_mega  <<<MEGA_GRID, 256>>>();     // 4  (ncu profiles launch #4)
    k_red1  <<<32, 256>>>();            // 5
    k_red2  <<<1, 32>>>(out);           // 6
}